// round 9
// baseline (speedup 1.0000x reference)
#include <cuda_runtime.h>

// SepKANLayer1D: per-token KAN edge-spline layer.
// x: (4, 8, 65536) f32, w: (4, 640, 65536) f32, out: (4, 8, 65536) f32.
// Pure HBM stream. 4 threads/token (OH=2). Per i-iteration:
//   (1) batch-issue all 20 streaming loads (shared base reg + imm offsets),
//   (2) closed-form uniform-knot cubic basis + silu (load-independent shim),
//   (3) consume.
// launch_bounds(128,14): 36-reg cap holds the full 20-deep batch while
// keeping 56 warp slots/SM (R8's 12-CTA cap cost more occupancy than the
// batching bought; this is the occ x MLP sweet spot).

#define IN_C   8
#define OUT_C  8
#define NB     8
#define OH     2                // outputs per thread
#define NTOK   65536
#define WSIZE  640

__global__ __launch_bounds__(128, 14)
void sepkan_kernel(const float* __restrict__ x,
                   const float* __restrict__ w,
                   float* __restrict__ out) {
    const int t = blockIdx.x * blockDim.x + threadIdx.x;   // 0 .. 262143 (token id)
    const int ob = blockIdx.y * OH;                        // 0,2,4,6
    const int b = t >> 16;
    const int n = t & (NTOK - 1);

    const float* xp = x + (size_t)b * IN_C * NTOK + n;
    const float* wp = w + (size_t)b * WSIZE * NTOK + n;

    float acc0 = 0.0f, acc1 = 0.0f;

    float xi_next = __ldg(xp);                 // prefetch channel 0

#pragma unroll 1
    for (int i = 0; i < IN_C; ++i) {
        const float xi = xi_next;

        // ---- (1) batch-issue the iteration's 20 streaming loads ----
        const float* wc = wp + (size_t)(i * OUT_C * NB + ob * NB) * NTOK;
        const float* wu = wp + (size_t)(IN_C * OUT_C * NB + i * OUT_C + ob) * NTOK;
        const float* wr = wp + (size_t)(IN_C * OUT_C * NB + IN_C * OUT_C + i * OUT_C + ob) * NTOK;

        float c[2 * NB];
#pragma unroll
        for (int k = 0; k < 2 * NB; ++k)
            c[k] = __ldcs(wc + (size_t)k * NTOK);
        const float u0 = __ldcs(wu);
        const float u1 = __ldcs(wu + NTOK);
        const float r0 = __ldcs(wr);
        const float r1 = __ldcs(wr + NTOK);

        if (i + 1 < IN_C) xi_next = __ldg(xp + (i + 1) * NTOK);

        // ---- (2) load-independent compute shim ----
        // closed-form uniform cubic B-spline, grid [0,1], 5 intervals:
        // m = clamp(floor(5x),0,4), u = 5x-m. Nonzero bases m..m+3:
        //   (1-u)^3/6, (3u^3-6u^2+4)/6, (-3u^3+3u^2+3u+1)/6, u^3/6
        int m = (int)(5.0f * xi);
        m = (m < 0) ? 0 : (m > 4 ? 4 : m);
        const float uu = 5.0f * xi - (float)m;
        const float vv = 1.0f - uu;
        const float uu2 = uu * uu, uu3 = uu2 * uu;
        const float bw0 = vv * vv * vv * (1.0f / 6.0f);
        const float bw1 = (3.0f * uu3 - 6.0f * uu2 + 4.0f) * (1.0f / 6.0f);
        const float bw2 = (-3.0f * uu3 + 3.0f * uu2 + 3.0f * uu + 1.0f) * (1.0f / 6.0f);
        const float bw3 = uu3 * (1.0f / 6.0f);

        float w8[NB];
#pragma unroll
        for (int k = 0; k < NB; ++k) {
            const int d = k - m;
            w8[k] = (d == 0) ? bw0 : (d == 1) ? bw1 : (d == 2) ? bw2 : (d == 3) ? bw3 : 0.0f;
        }

        const float sx = xi / (1.0f + __expf(-xi));   // silu

        // ---- (3) consume ----
        float sp0 = 0.0f, sp1 = 0.0f;
#pragma unroll
        for (int k = 0; k < NB; ++k) {
            sp0 = fmaf(w8[k], c[k],      sp0);
            sp1 = fmaf(w8[k], c[NB + k], sp1);
        }
        acc0 = fmaf(u0, sp0, acc0);
        acc1 = fmaf(u1, sp1, acc1);
        acc0 = fmaf(sx, r0, acc0);
        acc1 = fmaf(sx, r1, acc1);
    }

    float* yp = out + ((size_t)b * OUT_C + ob) * NTOK + n;
    yp[0]    = acc0;
    yp[NTOK] = acc1;
}

extern "C" void kernel_launch(void* const* d_in, const int* in_sizes, int n_in,
                              void* d_out, int out_size) {
    const float* x = (const float*)d_in[0];   // (4, 8, 65536)
    const float* w = (const float*)d_in[1];   // (4, 640, 65536)
    float* out = (float*)d_out;               // (4, 8, 65536)

    const int total = 4 * NTOK;               // 262144 tokens
    dim3 grid(total / 128, OUT_C / OH);       // (2048, 4)
    sepkan_kernel<<<grid, 128>>>(x, w, out);
}

// round 11
// speedup vs baseline: 1.0578x; 1.0578x over previous
#include <cuda_runtime.h>
#include <cstdint>

// SepKANLayer1D: per-token KAN edge-spline layer.
// x: (4, 8, 65536) f32, w: (4, 640, 65536) f32, out: (4, 8, 65536) f32.
// Pure HBM stream. 4 threads/token (OH=2). w loads go through cp.async
// (LDGSTS) into a per-thread double-buffered smem slab: in-flight depth is
// decoupled from the register file (no scoreboard regs held), so each warp
// keeps 2 stages x 20 requests in flight regardless of occupancy.
// Each thread consumes only the smem it wrote -> no __syncthreads needed.

#define IN_C   8
#define OUT_C  8
#define NB     8
#define OH     2                 // outputs per thread
#define NTOK   65536
#define WSIZE  640
#define STG    20                // floats staged per thread per iteration
#define TPB    128

__device__ __forceinline__ void cp4(unsigned int smem_dst, const float* gptr) {
    asm volatile("cp.async.ca.shared.global [%0], [%1], 4;\n"
                 :: "r"(smem_dst), "l"(gptr));
}
__device__ __forceinline__ void cp_commit() {
    asm volatile("cp.async.commit_group;\n" ::: "memory");
}
template <int N>
__device__ __forceinline__ void cp_wait() {
    asm volatile("cp.async.wait_group %0;\n" :: "n"(N) : "memory");
}

__global__ __launch_bounds__(TPB)
void sepkan_kernel(const float* __restrict__ x,
                   const float* __restrict__ w,
                   float* __restrict__ out) {
    __shared__ float buf[2][STG * TPB];      // 20 KB -> ~11 CTAs/SM

    const int tid = threadIdx.x;
    const int t = blockIdx.x * TPB + tid;    // 0 .. 262143 (token id)
    const int ob = blockIdx.y * OH;          // 0,2,4,6
    const int b = t >> 16;
    const int n = t & (NTOK - 1);

    const float* xp = x + (size_t)b * IN_C * NTOK + n;
    const float* wp = w + (size_t)b * WSIZE * NTOK + n;

    // per-thread smem base addresses (shared-state-space u32)
    unsigned int sbase[2];
    sbase[0] = (unsigned int)__cvta_generic_to_shared(&buf[0][tid]);
    sbase[1] = (unsigned int)__cvta_generic_to_shared(&buf[1][tid]);

    // ---- issue one stage of 20 cp.async loads for channel i into slot s ----
    auto issue = [&](int i, int s) {
        const float* wc = wp + (size_t)(i * OUT_C * NB + ob * NB) * NTOK;
        const float* wu = wp + (size_t)(IN_C * OUT_C * NB + i * OUT_C + ob) * NTOK;
        const float* wr = wp + (size_t)(IN_C * OUT_C * NB + IN_C * OUT_C + i * OUT_C + ob) * NTOK;
        const unsigned int sb = sbase[s];
#pragma unroll
        for (int k = 0; k < 2 * NB; ++k)
            cp4(sb + k * (TPB * 4), wc + (size_t)k * NTOK);
        cp4(sb + 16 * (TPB * 4), wu);
        cp4(sb + 17 * (TPB * 4), wu + NTOK);
        cp4(sb + 18 * (TPB * 4), wr);
        cp4(sb + 19 * (TPB * 4), wr + NTOK);
        cp_commit();
    };

    float acc0 = 0.0f, acc1 = 0.0f;
    float xi_next = __ldg(xp);               // prefetch channel 0's x

    issue(0, 0);                             // prologue

#pragma unroll 1
    for (int i = 0; i < IN_C; ++i) {
        const int s = i & 1;
        if (i + 1 < IN_C) issue(i + 1, s ^ 1);

        const float xi = xi_next;
        if (i + 1 < IN_C) xi_next = __ldg(xp + (i + 1) * NTOK);

        // ---- closed-form uniform cubic B-spline (load-independent) ----
        // m = clamp(floor(5x),0,4), u = 5x-m. Nonzero bases m..m+3:
        //   (1-u)^3/6, (3u^3-6u^2+4)/6, (-3u^3+3u^2+3u+1)/6, u^3/6
        int m = (int)(5.0f * xi);
        m = (m < 0) ? 0 : (m > 4 ? 4 : m);
        const float uu = 5.0f * xi - (float)m;
        const float vv = 1.0f - uu;
        const float uu2 = uu * uu, uu3 = uu2 * uu;
        const float bw0 = vv * vv * vv * (1.0f / 6.0f);
        const float bw1 = (3.0f * uu3 - 6.0f * uu2 + 4.0f) * (1.0f / 6.0f);
        const float bw2 = (-3.0f * uu3 + 3.0f * uu2 + 3.0f * uu + 1.0f) * (1.0f / 6.0f);
        const float bw3 = uu3 * (1.0f / 6.0f);

        float w8[NB];
#pragma unroll
        for (int k = 0; k < NB; ++k) {
            const int d = k - m;
            w8[k] = (d == 0) ? bw0 : (d == 1) ? bw1 : (d == 2) ? bw2 : (d == 3) ? bw3 : 0.0f;
        }
        const float sx = xi / (1.0f + __expf(-xi));   // silu

        // ---- wait for this stage only (next stage may stay in flight) ----
        if (i + 1 < IN_C) cp_wait<1>(); else cp_wait<0>();

        const float* sv = &buf[s][tid];      // stride TPB floats, conflict-free
        float sp0 = 0.0f, sp1 = 0.0f;
#pragma unroll
        for (int k = 0; k < NB; ++k) {
            sp0 = fmaf(w8[k], sv[k * TPB],        sp0);
            sp1 = fmaf(w8[k], sv[(NB + k) * TPB], sp1);
        }
        acc0 = fmaf(sv[16 * TPB], sp0, acc0);
        acc1 = fmaf(sv[17 * TPB], sp1, acc1);
        acc0 = fmaf(sx, sv[18 * TPB], acc0);
        acc1 = fmaf(sx, sv[19 * TPB], acc1);
    }

    float* yp = out + ((size_t)b * OUT_C + ob) * NTOK + n;
    yp[0]    = acc0;
    yp[NTOK] = acc1;
}

extern "C" void kernel_launch(void* const* d_in, const int* in_sizes, int n_in,
                              void* d_out, int out_size) {
    const float* x = (const float*)d_in[0];   // (4, 8, 65536)
    const float* w = (const float*)d_in[1];   // (4, 640, 65536)
    float* out = (float*)d_out;               // (4, 8, 65536)

    const int total = 4 * NTOK;               // 262144 tokens
    dim3 grid(total / TPB, OUT_C / OH);       // (2048, 4)
    sepkan_kernel<<<grid, TPB>>>(x, w, out);
}

// round 12
// speedup vs baseline: 1.4211x; 1.3435x over previous
#include <cuda_runtime.h>
#include <cstdint>

// SepKANLayer1D: per-token KAN edge-spline layer.
// x: (4, 8, 65536) f32, w: (4, 640, 65536) f32, out: (4, 8, 65536) f32.
// Cooperative-tile streaming: per i-iteration the CTA stages a 20-row x
// 128-token w tile into smem via 16B cp.async.cg (each warp fetches whole
// 512B rows: 32 lanes x 16B), double-buffered. 5 LDGSTS/thread/iter (vs 20
// scalar in the failed R11), L1-bypass, register-independent in-flight depth.
// Consume: conflict-free LDS (stride-128). 4 threads/token (OH=2 via grid.y).

#define IN_C   8
#define OUT_C  8
#define NB     8
#define OH     2
#define NTOK   65536
#define WSIZE  640
#define NROWS  20               // 16 coef + 2 uw + 2 rw rows per iteration
#define TPB    128

__device__ __forceinline__ void cp16(unsigned int smem_dst, const float* gptr) {
    asm volatile("cp.async.cg.shared.global [%0], [%1], 16;\n"
                 :: "r"(smem_dst), "l"(gptr));
}
__device__ __forceinline__ void cp_commit() {
    asm volatile("cp.async.commit_group;\n" ::: "memory");
}
template <int N>
__device__ __forceinline__ void cp_wait() {
    asm volatile("cp.async.wait_group %0;\n" :: "n"(N) : "memory");
}

__global__ __launch_bounds__(TPB, 11)
void sepkan_kernel(const float* __restrict__ x,
                   const float* __restrict__ w,
                   float* __restrict__ out) {
    __shared__ float buf[2][NROWS][TPB];     // 2 x 10 KB

    const int tid  = threadIdx.x;
    const int lane = tid & 31;
    const int wid  = tid >> 5;
    const int ob = blockIdx.y * OH;          // 0,2,4,6
    const int b  = blockIdx.x >> 9;          // 512 token-blocks per batch
    const int n0 = (blockIdx.x & 511) * TPB; // token base of this CTA
    const int n  = n0 + tid;

    const float* xp = x + (size_t)b * IN_C * NTOK + n;
    // per-lane source base: row start + this lane's 16B chunk
    const float* wbase = w + (size_t)b * WSIZE * NTOK + n0 + lane * 4;

    // stage one iteration's 20-row tile into buffer s.
    // warp `wid` loads rows {wid, 4+wid, 8+wid, 12+wid, 16+wid};
    // one LDGSTS.16 per lane covers a full 512B row per (warp, q).
    auto issue = [&](int i, int s) {
#pragma unroll
        for (int q = 0; q < 5; ++q) {
            const int r = 4 * q + wid;       // local row 0..19
            int gr;                          // global w row
            if (r < 16)      gr = i * OUT_C * NB + ob * NB + r;
            else if (r < 18) gr = IN_C * OUT_C * NB + i * OUT_C + ob + (r - 16);
            else             gr = IN_C * OUT_C * NB + IN_C * OUT_C + i * OUT_C + ob + (r - 18);
            const unsigned int dst =
                (unsigned int)__cvta_generic_to_shared(&buf[s][r][lane * 4]);
            cp16(dst, wbase + (size_t)gr * NTOK);
        }
        cp_commit();
    };

    float acc0 = 0.0f, acc1 = 0.0f;
    float xi_next = __ldg(xp);               // prefetch channel 0's x

    issue(0, 0);                             // prologue

#pragma unroll 1
    for (int i = 0; i < IN_C; ++i) {
        const int s = i & 1;
        if (i + 1 < IN_C) issue(i + 1, s ^ 1);

        const float xi = xi_next;
        if (i + 1 < IN_C) xi_next = __ldg(xp + (i + 1) * NTOK);

        // ---- closed-form uniform cubic B-spline (load-independent shim) ----
        // m = clamp(floor(5x),0,4), u = 5x-m. Nonzero bases m..m+3:
        //   (1-u)^3/6, (3u^3-6u^2+4)/6, (-3u^3+3u^2+3u+1)/6, u^3/6
        int m = (int)(5.0f * xi);
        m = (m < 0) ? 0 : (m > 4 ? 4 : m);
        const float uu = 5.0f * xi - (float)m;
        const float vv = 1.0f - uu;
        const float uu2 = uu * uu, uu3 = uu2 * uu;
        const float bw0 = vv * vv * vv * (1.0f / 6.0f);
        const float bw1 = (3.0f * uu3 - 6.0f * uu2 + 4.0f) * (1.0f / 6.0f);
        const float bw2 = (-3.0f * uu3 + 3.0f * uu2 + 3.0f * uu + 1.0f) * (1.0f / 6.0f);
        const float bw3 = uu3 * (1.0f / 6.0f);

        float w8[NB];
#pragma unroll
        for (int k = 0; k < NB; ++k) {
            const int d = k - m;
            w8[k] = (d == 0) ? bw0 : (d == 1) ? bw1 : (d == 2) ? bw2 : (d == 3) ? bw3 : 0.0f;
        }
        const float sx = xi / (1.0f + __expf(-xi));   // silu

        // ---- wait for stage s (stage s+1 stays in flight), make visible ----
        if (i + 1 < IN_C) cp_wait<1>(); else cp_wait<0>();
        __syncthreads();                     // stage s complete for ALL threads

        float sp0 = 0.0f, sp1 = 0.0f;
#pragma unroll
        for (int k = 0; k < NB; ++k) {
            sp0 = fmaf(w8[k], buf[s][k][tid],      sp0);
            sp1 = fmaf(w8[k], buf[s][NB + k][tid], sp1);
        }
        acc0 = fmaf(buf[s][16][tid], sp0, acc0);
        acc1 = fmaf(buf[s][17][tid], sp1, acc1);
        acc0 = fmaf(sx, buf[s][18][tid], acc0);
        acc1 = fmaf(sx, buf[s][19][tid], acc1);

        __syncthreads();                     // all reads of s done before i+2 overwrites
    }

    float* yp = out + ((size_t)b * OUT_C + ob) * NTOK + n;
    yp[0]    = acc0;
    yp[NTOK] = acc1;
}

extern "C" void kernel_launch(void* const* d_in, const int* in_sizes, int n_in,
                              void* d_out, int out_size) {
    const float* x = (const float*)d_in[0];   // (4, 8, 65536)
    const float* w = (const float*)d_in[1];   // (4, 640, 65536)
    float* out = (float*)d_out;               // (4, 8, 65536)

    const int total = 4 * NTOK;               // 262144 tokens
    dim3 grid(total / TPB, OUT_C / OH);       // (2048, 4)
    sepkan_kernel<<<grid, TPB>>>(x, w, out);
}

// round 13
// speedup vs baseline: 1.4763x; 1.0388x over previous
#include <cuda_runtime.h>
#include <cstdint>

// SepKANLayer1D: per-token KAN edge-spline layer.
// x: (4, 8, 65536) f32, w: (4, 640, 65536) f32, out: (4, 8, 65536) f32.
// Cooperative-tile streaming (R12) + issue-diet (R13):
//  - 16 coef rows staged per iteration via 16B cp.async.cg, double-buffered
//    (16 KB/CTA -> 12 CTAs/SM); uw/rw via direct __ldcs (4 regs).
//  - consume uses dynamic 4-of-8 gather: only bases m..m+3 are nonzero, and
//    smem row indexing is conflict-free for any m (row stride 128 = 0 mod 32).
// 4 threads/token (OH=2 via grid.y).

#define IN_C   8
#define OUT_C  8
#define NB     8
#define OH     2
#define NTOK   65536
#define WSIZE  640
#define NROWS  16               // coef rows staged per iteration
#define TPB    128

__device__ __forceinline__ void cp16(unsigned int smem_dst, const float* gptr) {
    asm volatile("cp.async.cg.shared.global [%0], [%1], 16;\n"
                 :: "r"(smem_dst), "l"(gptr));
}
__device__ __forceinline__ void cp_commit() {
    asm volatile("cp.async.commit_group;\n" ::: "memory");
}
template <int N>
__device__ __forceinline__ void cp_wait() {
    asm volatile("cp.async.wait_group %0;\n" :: "n"(N) : "memory");
}

__global__ __launch_bounds__(TPB, 12)
void sepkan_kernel(const float* __restrict__ x,
                   const float* __restrict__ w,
                   float* __restrict__ out) {
    __shared__ float buf[2][NROWS][TPB];     // 2 x 8 KB

    const int tid  = threadIdx.x;
    const int lane = tid & 31;
    const int wid  = tid >> 5;
    const int ob = blockIdx.y * OH;          // 0,2,4,6
    const int b  = blockIdx.x >> 9;          // 512 token-blocks per batch
    const int n0 = (blockIdx.x & 511) * TPB; // token base of this CTA
    const int n  = n0 + tid;

    const float* xp = x + (size_t)b * IN_C * NTOK + n;
    const float* wp = w + (size_t)b * WSIZE * NTOK + n;       // per-thread (uw/rw)
    const float* wbase = w + (size_t)b * WSIZE * NTOK + n0 + lane * 4;  // per-lane 16B chunk

    // stage one iteration's 16 coef rows into buffer s.
    // warp `wid` loads rows {wid, 4+wid, 8+wid, 12+wid}: one LDGSTS.16 per
    // lane covers a full 512B row per (warp, q).
    auto issue = [&](int i, int s) {
#pragma unroll
        for (int q = 0; q < 4; ++q) {
            const int r = 4 * q + wid;       // local coef row 0..15
            const int gr = i * OUT_C * NB + ob * NB + r;
            const unsigned int dst =
                (unsigned int)__cvta_generic_to_shared(&buf[s][r][lane * 4]);
            cp16(dst, wbase + (size_t)gr * NTOK);
        }
        cp_commit();
    };

    float acc0 = 0.0f, acc1 = 0.0f;
    float xi_next = __ldg(xp);               // prefetch channel 0's x

    issue(0, 0);                             // prologue

#pragma unroll 1
    for (int i = 0; i < IN_C; ++i) {
        const int s = i & 1;
        if (i + 1 < IN_C) issue(i + 1, s ^ 1);

        // uw/rw direct streaming loads for this iteration (batched early)
        const float* wu = wp + (size_t)(IN_C * OUT_C * NB + i * OUT_C + ob) * NTOK;
        const float* wr = wp + (size_t)(IN_C * OUT_C * NB + IN_C * OUT_C + i * OUT_C + ob) * NTOK;
        const float u0 = __ldcs(wu);
        const float u1 = __ldcs(wu + NTOK);
        const float r0 = __ldcs(wr);
        const float r1 = __ldcs(wr + NTOK);

        const float xi = xi_next;
        if (i + 1 < IN_C) xi_next = __ldg(xp + (i + 1) * NTOK);

        // ---- closed-form uniform cubic B-spline (load-independent shim) ----
        // m = clamp(floor(5x),0,4), u = 5x-m. Nonzero bases m..m+3:
        //   (1-u)^3/6, (3u^3-6u^2+4)/6, (-3u^3+3u^2+3u+1)/6, u^3/6
        int m = (int)(5.0f * xi);
        m = (m < 0) ? 0 : (m > 4 ? 4 : m);
        const float uu = 5.0f * xi - (float)m;
        const float vv = 1.0f - uu;
        const float uu2 = uu * uu, uu3 = uu2 * uu;
        float bw[4];
        bw[0] = vv * vv * vv * (1.0f / 6.0f);
        bw[1] = (3.0f * uu3 - 6.0f * uu2 + 4.0f) * (1.0f / 6.0f);
        bw[2] = (-3.0f * uu3 + 3.0f * uu2 + 3.0f * uu + 1.0f) * (1.0f / 6.0f);
        bw[3] = uu3 * (1.0f / 6.0f);

        const float sx = xi / (1.0f + __expf(-xi));   // silu

        // ---- wait for stage s (stage s+1 stays in flight), make visible ----
        if (i + 1 < IN_C) cp_wait<1>(); else cp_wait<0>();
        __syncthreads();

        // dynamic 4-of-8 gather: rows m..m+3 (o=ob) and 8+m..8+m+3 (o=ob+1).
        // address bank = tid%32 regardless of m -> conflict-free.
        const float* sv = &buf[s][0][tid];
        float sp0 = 0.0f, sp1 = 0.0f;
#pragma unroll
        for (int j = 0; j < 4; ++j) {
            sp0 = fmaf(bw[j], sv[(m + j) * TPB],      sp0);
            sp1 = fmaf(bw[j], sv[(NB + m + j) * TPB], sp1);
        }
        acc0 = fmaf(u0, sp0, acc0);
        acc1 = fmaf(u1, sp1, acc1);
        acc0 = fmaf(sx, r0, acc0);
        acc1 = fmaf(sx, r1, acc1);

        __syncthreads();                     // reads of s done before i+2 overwrites
    }

    float* yp = out + ((size_t)b * OUT_C + ob) * NTOK + n;
    yp[0]    = acc0;
    yp[NTOK] = acc1;
}

extern "C" void kernel_launch(void* const* d_in, const int* in_sizes, int n_in,
                              void* d_out, int out_size) {
    const float* x = (const float*)d_in[0];   // (4, 8, 65536)
    const float* w = (const float*)d_in[1];   // (4, 640, 65536)
    float* out = (float*)d_out;               // (4, 8, 65536)

    const int total = 4 * NTOK;               // 262144 tokens
    dim3 grid(total / TPB, OUT_C / OH);       // (2048, 4)
    sepkan_kernel<<<grid, TPB>>>(x, w, out);
}

// round 14
// speedup vs baseline: 1.4785x; 1.0015x over previous
#include <cuda_runtime.h>
#include <cstdint>

// SepKANLayer1D: per-token KAN edge-spline layer.
// x: (4, 8, 65536) f32, w: (4, 640, 65536) f32, out: (4, 8, 65536) f32.
// Persistent cooperative-tile streaming: 1024 CTAs, each owns 8 consecutive
// (128-token x ob-slice) units = 64 jobs, double-buffered 16B cp.async.cg
// pipeline runs continuously across unit boundaries (single wave, one drain,
// no wave-transition bubbles, perfectly balanced 8 units/CTA).
// Consume: dynamic 4-of-8 gather (only bases m..m+3 nonzero; conflict-free).

#define IN_C   8
#define OUT_C  8
#define NB     8
#define OH     2
#define NTOK   65536
#define WSIZE  640
#define NROWS  16               // coef rows staged per job
#define TPB    128
#define NCTAS  1024
#define UPC    8                // units per CTA
#define NJOBS  (UPC * IN_C)     // 64 jobs per CTA

__device__ __forceinline__ void cp16(unsigned int smem_dst, const float* gptr) {
    asm volatile("cp.async.cg.shared.global [%0], [%1], 16;\n"
                 :: "r"(smem_dst), "l"(gptr));
}
__device__ __forceinline__ void cp_commit() {
    asm volatile("cp.async.commit_group;\n" ::: "memory");
}
template <int N>
__device__ __forceinline__ void cp_wait() {
    asm volatile("cp.async.wait_group %0;\n" :: "n"(N) : "memory");
}

// unit id -> (b, n0, ob):  unit = obi*2048 + blk;  blk = b*512 + blk_in_b
__device__ __forceinline__ void unit_decode(int unit, int& b, int& n0, int& ob) {
    const int obi = unit >> 11;
    const int blk = unit & 2047;
    b  = blk >> 9;
    n0 = (blk & 511) * TPB;
    ob = obi * OH;
}

__global__ __launch_bounds__(TPB, 8)
void sepkan_kernel(const float* __restrict__ x,
                   const float* __restrict__ w,
                   float* __restrict__ out) {
    __shared__ float buf[2][NROWS][TPB];     // 2 x 8 KB

    const int tid  = threadIdx.x;
    const int lane = tid & 31;
    const int wid  = tid >> 5;
    const int u_base = blockIdx.x * UPC;

    // stage job j's 16 coef rows into buffer slot s.
    // warp `wid` loads rows {wid, 4+wid, 8+wid, 12+wid}; one LDGSTS.16 per
    // lane covers a full 512B row per (warp, q).
    auto issue = [&](int j, int s) {
        const int unit = u_base + (j >> 3);
        const int i = j & 7;
        int b, n0, ob;
        unit_decode(unit, b, n0, ob);
        const float* wbase = w + (size_t)b * WSIZE * NTOK + n0 + lane * 4;
#pragma unroll
        for (int q = 0; q < 4; ++q) {
            const int r = 4 * q + wid;       // local coef row 0..15
            const int gr = i * OUT_C * NB + ob * NB + r;
            const unsigned int dst =
                (unsigned int)__cvta_generic_to_shared(&buf[s][r][lane * 4]);
            cp16(dst, wbase + (size_t)gr * NTOK);
        }
        cp_commit();
    };

    float acc0 = 0.0f, acc1 = 0.0f;

    // prefetch x for job 0
    float xi_next;
    {
        int b, n0, ob;
        unit_decode(u_base, b, n0, ob);
        xi_next = __ldg(x + (size_t)b * IN_C * NTOK + n0 + tid);
    }

    issue(0, 0);                             // prologue

#pragma unroll 1
    for (int j = 0; j < NJOBS; ++j) {
        const int s = j & 1;
        if (j + 1 < NJOBS) issue(j + 1, s ^ 1);

        const int unit = u_base + (j >> 3);
        const int i = j & 7;
        int b, n0, ob;
        unit_decode(unit, b, n0, ob);
        const int n = n0 + tid;
        const float* wp = w + (size_t)b * WSIZE * NTOK + n;

        // uw/rw direct streaming loads (latency overlapped with stage wait)
        const float* wu = wp + (size_t)(IN_C * OUT_C * NB + i * OUT_C + ob) * NTOK;
        const float* wr = wp + (size_t)(IN_C * OUT_C * NB + IN_C * OUT_C + i * OUT_C + ob) * NTOK;
        const float u0v = __ldcs(wu);
        const float u1v = __ldcs(wu + NTOK);
        const float r0v = __ldcs(wr);
        const float r1v = __ldcs(wr + NTOK);

        const float xi = xi_next;
        if (j + 1 < NJOBS) {                 // prefetch x for job j+1
            const int unit1 = u_base + ((j + 1) >> 3);
            const int i1 = (j + 1) & 7;
            int b1, n01, ob1;
            unit_decode(unit1, b1, n01, ob1);
            xi_next = __ldg(x + (size_t)b1 * IN_C * NTOK + (size_t)i1 * NTOK + n01 + tid);
        }

        if (i == 0) { acc0 = 0.0f; acc1 = 0.0f; }

        // ---- closed-form uniform cubic B-spline (load-independent shim) ----
        // m = clamp(floor(5x),0,4), u = 5x-m. Nonzero bases m..m+3:
        //   (1-u)^3/6, (3u^3-6u^2+4)/6, (-3u^3+3u^2+3u+1)/6, u^3/6
        int m = (int)(5.0f * xi);
        m = (m < 0) ? 0 : (m > 4 ? 4 : m);
        const float uu = 5.0f * xi - (float)m;
        const float vv = 1.0f - uu;
        const float uu2 = uu * uu, uu3 = uu2 * uu;
        float bw[4];
        bw[0] = vv * vv * vv * (1.0f / 6.0f);
        bw[1] = (3.0f * uu3 - 6.0f * uu2 + 4.0f) * (1.0f / 6.0f);
        bw[2] = (-3.0f * uu3 + 3.0f * uu2 + 3.0f * uu + 1.0f) * (1.0f / 6.0f);
        bw[3] = uu3 * (1.0f / 6.0f);

        const float sx = xi / (1.0f + __expf(-xi));   // silu

        // ---- wait for stage s (stage s+1 stays in flight), make visible ----
        if (j + 1 < NJOBS) cp_wait<1>(); else cp_wait<0>();
        __syncthreads();

        // dynamic 4-of-8 gather: rows m..m+3 (o=ob) and 8+m..8+m+3 (o=ob+1).
        const float* sv = &buf[s][0][tid];
        float sp0 = 0.0f, sp1 = 0.0f;
#pragma unroll
        for (int jj = 0; jj < 4; ++jj) {
            sp0 = fmaf(bw[jj], sv[(m + jj) * TPB],      sp0);
            sp1 = fmaf(bw[jj], sv[(NB + m + jj) * TPB], sp1);
        }
        acc0 = fmaf(u0v, sp0, acc0);
        acc1 = fmaf(u1v, sp1, acc1);
        acc0 = fmaf(sx, r0v, acc0);
        acc1 = fmaf(sx, r1v, acc1);

        __syncthreads();                     // reads of s done before j+2 overwrites

        if (i == IN_C - 1) {
            float* yp = out + ((size_t)b * OUT_C + ob) * NTOK + n;
            __stcs(yp, acc0);
            __stcs(yp + NTOK, acc1);
        }
    }
}

extern "C" void kernel_launch(void* const* d_in, const int* in_sizes, int n_in,
                              void* d_out, int out_size) {
    const float* x = (const float*)d_in[0];   // (4, 8, 65536)
    const float* w = (const float*)d_in[1];   // (4, 640, 65536)
    float* out = (float*)d_out;               // (4, 8, 65536)

    sepkan_kernel<<<NCTAS, TPB>>>(x, w, out); // 1024 persistent CTAs, 1 wave
}